// round 1
// baseline (speedup 1.0000x reference)
#include <cuda_runtime.h>
#include <cstdint>
#include <math.h>

#define DEV_INLINE __device__ __forceinline__

// ---------------- problem constants ----------------
constexpr int Bb  = 8;
constexpr int Ll  = 256;
constexpr int Hh  = 512;
constexpr int Vv  = 32000;
constexpr int DI  = 1024;
constexpr int DS  = 16;
constexpr int DTR = 32;
constexpr int Mm  = Bb * Ll;          // 2048 rows
constexpr int TAa = 200, TTt = 100, ADa = 1024, TDd = 1024;

// ---------------- scratch (static device globals; no allocs allowed) ----------------
__device__ float g_x   [Mm * Hh];        // running hidden state (B,L,H)
__device__ float g_xz  [Mm * 2 * DI];    // in_proj output
__device__ float g_xc  [Mm * DI];        // conv+silu output
__device__ float g_dbl [Mm * 64];        // x_proj output (dt_in | B | C)
__device__ float g_dt  [Mm * DI];        // softplus dt
__device__ float g_y   [Mm * DI];        // scan output (gated)
__device__ float g_yt  [Mm * Hh];        // out_proj output
__device__ float g_sa  [Bb * ADa];
__device__ float g_st  [Bb * TDd];
__device__ float g_pooled[Bb * Hh];
__device__ float g_cond  [Bb * Hh];

// ---------------- helpers ----------------
DEV_INLINE float warp_sum(float v) {
    #pragma unroll
    for (int o = 16; o; o >>= 1) v += __shfl_xor_sync(0xffffffffu, v, o);
    return v;
}
DEV_INLINE float softplus_f(float x) {
    return x > 20.f ? x : log1pf(__expf(x));
}
DEV_INLINE float silu_f(float x) {
    return x / (1.f + __expf(-x));
}

// ---------------- generic NT SGEMM: C[m,n] = sum_k A[m,k]*B[n,k] (+bias, epi) ----------------
// EPI: 0 = none, 1 = +bias, 2 = softplus(+bias)
template<int BM, int BN, int BK, int TM, int TN, int EPI>
__global__ void gemm_nt(const float* __restrict__ A, const float* __restrict__ Bp,
                        const float* __restrict__ bias, float* __restrict__ C,
                        int M, int N, int K, int lda, int ldb, int ldc)
{
    constexpr int TX = BN / TN;
    constexpr int TY = BM / TM;
    constexpr int NT = TX * TY;           // threads per block
    constexpr int KC4 = BK / 4;
    __shared__ float As[BK][BM + 4];
    __shared__ float Bs[BK][BN + 4];

    const int tid = threadIdx.x;
    const int tx = tid % TX, ty = tid / TX;
    const int bm = blockIdx.x * BM, bn = blockIdx.y * BN;

    float acc[TM][TN];
    #pragma unroll
    for (int i = 0; i < TM; i++)
        #pragma unroll
        for (int j = 0; j < TN; j++) acc[i][j] = 0.f;

    for (int k0 = 0; k0 < K; k0 += BK) {
        for (int f = tid; f < BM * KC4; f += NT) {
            int row = f / KC4, c = f % KC4;
            float4 v = *reinterpret_cast<const float4*>(A + (size_t)(bm + row) * lda + k0 + c * 4);
            As[c*4+0][row] = v.x; As[c*4+1][row] = v.y;
            As[c*4+2][row] = v.z; As[c*4+3][row] = v.w;
        }
        for (int f = tid; f < BN * KC4; f += NT) {
            int row = f / KC4, c = f % KC4;
            float4 v = *reinterpret_cast<const float4*>(Bp + (size_t)(bn + row) * ldb + k0 + c * 4);
            Bs[c*4+0][row] = v.x; Bs[c*4+1][row] = v.y;
            Bs[c*4+2][row] = v.z; Bs[c*4+3][row] = v.w;
        }
        __syncthreads();
        #pragma unroll
        for (int k = 0; k < BK; k++) {
            float a[TM], b[TN];
            #pragma unroll
            for (int i = 0; i < TM; i++) a[i] = As[k][ty * TM + i];
            #pragma unroll
            for (int j = 0; j < TN; j++) b[j] = Bs[k][tx * TN + j];
            #pragma unroll
            for (int i = 0; i < TM; i++)
                #pragma unroll
                for (int j = 0; j < TN; j++) acc[i][j] += a[i] * b[j];
        }
        __syncthreads();
    }

    #pragma unroll
    for (int i = 0; i < TM; i++) {
        int m = bm + ty * TM + i;
        float4 o;
        float* op = &o.x;
        #pragma unroll
        for (int j = 0; j < TN; j++) {
            float v = acc[i][j];
            if (EPI >= 1) v += bias[bn + tx * TN + j];
            if (EPI == 2) v = softplus_f(v);
            op[j] = v;
        }
        *reinterpret_cast<float4*>(C + (size_t)m * ldc + bn + tx * TN) = o;
    }
}

// ---------------- conditioning path ----------------
// masked token-sums of audio / text features (collapses the big memory GEMM to a GEMV)
__global__ void sums_kernel(const float* __restrict__ af, const float* __restrict__ tf,
                            const unsigned char* __restrict__ am, const unsigned char* __restrict__ tm,
                            float* __restrict__ sa, float* __restrict__ st)
{
    int k = blockIdx.x * 256 + threadIdx.x;   // 0..1023
    int b = blockIdx.y;
    float s = 0.f;
    for (int t = 0; t < TAa; t++)
        if (!am[b * TAa + t]) s += af[((size_t)(b * TAa + t)) * ADa + k];
    sa[b * ADa + k] = s;
    s = 0.f;
    for (int t = 0; t < TTt; t++)
        if (!tm[b * TTt + t]) s += tf[((size_t)(b * TTt + t)) * TDd + k];
    st[b * TDd + k] = s;
}

__global__ void pooled_kernel(const float* __restrict__ sa, const float* __restrict__ st,
                              const unsigned char* __restrict__ am, const unsigned char* __restrict__ tm,
                              const float* __restrict__ aw, const float* __restrict__ tw,
                              const float* __restrict__ ab, const float* __restrict__ tb,
                              const float* __restrict__ me, float* __restrict__ pooled)
{
    int b = blockIdx.x, tid = threadIdx.x, lane = tid & 31, w = tid >> 5;
    // every thread computes the counts redundantly (tiny broadcast loads)
    float na = 0.f, nt = 0.f;
    for (int t = 0; t < TAa; t++) na += am[b * TAa + t] ? 0.f : 1.f;
    for (int t = 0; t < TTt; t++) nt += tm[b * TTt + t] ? 0.f : 1.f;
    float denom = fmaxf(na + nt, 1.f);

    for (int h = w; h < Hh; h += 8) {
        float s = 0.f;
        for (int k = lane; k < ADa; k += 32)
            s += sa[b * ADa + k] * aw[(size_t)h * ADa + k]
               + st[b * TDd + k] * tw[(size_t)h * TDd + k];
        s = warp_sum(s);
        if (lane == 0) {
            float v = s + na * (ab[h] + me[h]) + nt * (tb[h] + me[Hh + h]);
            pooled[b * Hh + h] = v / denom;
        }
    }
}

__global__ void cond_kernel(const float* __restrict__ pooled, const float* __restrict__ cw,
                            const float* __restrict__ cb, float* __restrict__ cond)
{
    int b = blockIdx.x, tid = threadIdx.x, lane = tid & 31, w = tid >> 5;
    for (int h = w; h < Hh; h += 8) {
        float s = 0.f;
        for (int k = lane; k < Hh; k += 32)
            s += pooled[b * Hh + k] * cw[(size_t)h * Hh + k];
        s = warp_sum(s);
        if (lane == 0) cond[b * Hh + h] = s + cb[h];
    }
}

__global__ void embed_kernel(const int* __restrict__ ids, const float* __restrict__ te,
                             const float* __restrict__ pe, const float* __restrict__ cond,
                             float* __restrict__ x)
{
    int idx = blockIdx.x * 256 + threadIdx.x;  // Mm*Hh
    int h = idx & (Hh - 1);
    int m = idx >> 9;
    int l = m & (Ll - 1);
    int b = m >> 8;
    x[idx] = te[(size_t)ids[m] * Hh + h] + pe[l * Hh + h] + cond[b * Hh + h];
}

// ---------------- mamba internals ----------------
__global__ void conv_silu_kernel(const float* __restrict__ xz, const float* __restrict__ cw,
                                 const float* __restrict__ cb, float* __restrict__ xc)
{
    int idx = blockIdx.x * 256 + threadIdx.x;   // Mm*DI
    int d = idx & (DI - 1);
    int m = idx >> 10;
    int t = m & (Ll - 1);
    float acc = cb[d];
    #pragma unroll
    for (int k = 0; k < 4; k++) {
        int tt = t + k - 3;
        if (tt >= 0) acc += xz[(size_t)(m + k - 3) * (2 * DI) + d] * cw[d * 4 + k];
    }
    xc[idx] = silu_f(acc);
}

// selective scan: 4 state-slots per thread, 16-per-(b,d) via 4-lane groups.
// fuses dA/dBu computation, the C-contraction, D-skip, and silu(z) gating.
__global__ void scan_kernel(const float* __restrict__ dt, const float* __restrict__ xc,
                            const float* __restrict__ dbl, const float* __restrict__ xz,
                            const float* __restrict__ Alog, const float* __restrict__ Dp,
                            float* __restrict__ y)
{
    int b = blockIdx.y;
    int sq = threadIdx.x & 3;          // which 4-slot group of the 16 states
    int dloc = threadIdx.x >> 2;       // 0..63
    int d = blockIdx.x * 64 + dloc;

    float Av[4];
    #pragma unroll
    for (int j = 0; j < 4; j++) Av[j] = -__expf(Alog[d * DS + sq * 4 + j]);
    float h[4] = {0.f, 0.f, 0.f, 0.f};
    float Dd = Dp[d];

    int mbase = b * Ll;
    for (int t = 0; t < Ll; t++) {
        int m = mbase + t;
        float dtv = dt[(size_t)m * DI + d];
        float xcv = xc[(size_t)m * DI + d];
        float u = dtv * xcv;
        const float* dm = dbl + (size_t)m * 64;
        float yp = 0.f;
        #pragma unroll
        for (int j = 0; j < 4; j++) {
            float Bv = dm[DTR + sq * 4 + j];
            float Cv = dm[DTR + DS + sq * 4 + j];
            float e = __expf(dtv * Av[j]);
            h[j] = h[j] * e + u * Bv;
            yp += h[j] * Cv;
        }
        yp += __shfl_xor_sync(0xffffffffu, yp, 1);
        yp += __shfl_xor_sync(0xffffffffu, yp, 2);
        if (sq == 0) {
            float zv = xz[(size_t)m * (2 * DI) + DI + d];
            y[(size_t)m * DI + d] = (yp + Dd * xcv) * silu_f(zv);
        }
    }
}

// residual add + layernorm, in place on g_x. one block per row.
__global__ void ln_kernel(float* __restrict__ x, const float* __restrict__ yt,
                          const float* __restrict__ g, const float* __restrict__ bb)
{
    int m = blockIdx.x;
    int tid = threadIdx.x;     // 128 threads, 4 elems each
    float v[4];
    float s = 0.f;
    #pragma unroll
    for (int j = 0; j < 4; j++) {
        int h = tid + j * 128;
        v[j] = x[(size_t)m * Hh + h] + yt[(size_t)m * Hh + h];
        s += v[j];
    }
    __shared__ float red[4];
    __shared__ float red2[4];
    s = warp_sum(s);
    if ((tid & 31) == 0) red[tid >> 5] = s;
    __syncthreads();
    float mu = (red[0] + red[1] + red[2] + red[3]) * (1.f / Hh);
    float s2 = 0.f;
    #pragma unroll
    for (int j = 0; j < 4; j++) { float dv = v[j] - mu; s2 += dv * dv; }
    s2 = warp_sum(s2);
    if ((tid & 31) == 0) red2[tid >> 5] = s2;
    __syncthreads();
    float var = (red2[0] + red2[1] + red2[2] + red2[3]) * (1.f / Hh);
    float sc = rsqrtf(var + 1e-5f);
    #pragma unroll
    for (int j = 0; j < 4; j++) {
        int h = tid + j * 128;
        x[(size_t)m * Hh + h] = (v[j] - mu) * sc * g[h] + bb[h];
    }
}

// ---------------- launch ----------------
extern "C" void kernel_launch(void* const* d_in, const int* in_sizes, int n_in,
                              void* d_out, int out_size)
{
    const int*   ids  = (const int*)  d_in[0];
    const float* af   = (const float*)d_in[1];
    const float* tf   = (const float*)d_in[2];
    const unsigned char* am = (const unsigned char*)d_in[3];
    const unsigned char* tm = (const unsigned char*)d_in[4];
    const float* te   = (const float*)d_in[5];
    const float* pe   = (const float*)d_in[6];
    const float* aw   = (const float*)d_in[7];
    const float* ab   = (const float*)d_in[8];
    const float* tw   = (const float*)d_in[9];
    const float* tb   = (const float*)d_in[10];
    const float* me   = (const float*)d_in[11];
    const float* cw   = (const float*)d_in[12];
    const float* cb   = (const float*)d_in[13];
    const float* ipw  = (const float*)d_in[14];
    const float* convw= (const float*)d_in[15];
    const float* convb= (const float*)d_in[16];
    const float* xpw  = (const float*)d_in[17];
    const float* dtw  = (const float*)d_in[18];
    const float* dtb  = (const float*)d_in[19];
    const float* Alog = (const float*)d_in[20];
    const float* Dp   = (const float*)d_in[21];
    const float* ow   = (const float*)d_in[22];
    const float* lng  = (const float*)d_in[23];
    const float* lnb  = (const float*)d_in[24];
    const float* hw   = (const float*)d_in[25];
    const float* hb   = (const float*)d_in[26];
    float* out = (float*)d_out;

    float *x, *xz, *xc, *dbl, *dt, *y, *yt, *sa, *st, *pooled, *cond;
    cudaGetSymbolAddress((void**)&x,   g_x);
    cudaGetSymbolAddress((void**)&xz,  g_xz);
    cudaGetSymbolAddress((void**)&xc,  g_xc);
    cudaGetSymbolAddress((void**)&dbl, g_dbl);
    cudaGetSymbolAddress((void**)&dt,  g_dt);
    cudaGetSymbolAddress((void**)&y,   g_y);
    cudaGetSymbolAddress((void**)&yt,  g_yt);
    cudaGetSymbolAddress((void**)&sa,  g_sa);
    cudaGetSymbolAddress((void**)&st,  g_st);
    cudaGetSymbolAddress((void**)&pooled, g_pooled);
    cudaGetSymbolAddress((void**)&cond,   g_cond);

    // conditioning
    sums_kernel  <<<dim3(ADa / 256, Bb), 256>>>(af, tf, am, tm, sa, st);
    pooled_kernel<<<Bb, 256>>>(sa, st, am, tm, aw, tw, ab, tb, me, pooled);
    cond_kernel  <<<Bb, 256>>>(pooled, cw, cb, cond);
    embed_kernel <<<(Mm * Hh) / 256, 256>>>(ids, te, pe, cond, x);

    for (int i = 0; i < 6; i++) {
        // xz = x @ in_proj.T            (2048 x 2048 x 512)
        gemm_nt<128,64,16,8,4,0><<<dim3(Mm/128, (2*DI)/64), 256>>>(
            x, ipw + (size_t)i * 2 * DI * Hh, nullptr, xz,
            Mm, 2*DI, Hh, Hh, Hh, 2*DI);
        // xc = silu(causal_conv(xz[:, :DI]))
        conv_silu_kernel<<<(Mm * DI) / 256, 256>>>(xz, convw + (size_t)i * DI * 4,
                                                   convb + (size_t)i * DI, xc);
        // dbl = xc @ x_proj.T           (2048 x 64 x 1024)
        gemm_nt<16,64,32,1,4,0><<<dim3(Mm/16, 1), 256>>>(
            xc, xpw + (size_t)i * 64 * DI, nullptr, dbl,
            Mm, 64, DI, DI, DI, 64);
        // dt = softplus(dbl[:, :32] @ dt_w.T + dt_b)   (2048 x 1024 x 32)
        gemm_nt<16,64,32,1,4,2><<<dim3(Mm/16, DI/64), 256>>>(
            dbl, dtw + (size_t)i * DI * DTR, dtb + (size_t)i * DI, dt,
            Mm, DI, DTR, 64, DTR, DI);
        // selective scan (fused dA/dBu/C-contract/D-skip/gate)
        scan_kernel<<<dim3(DI/64, Bb), 256>>>(dt, xc, dbl, xz,
                                              Alog + (size_t)i * DI * DS,
                                              Dp + (size_t)i * DI, y);
        // yt = y @ out_w.T              (2048 x 512 x 1024)
        gemm_nt<128,64,16,8,4,0><<<dim3(Mm/128, Hh/64), 256>>>(
            y, ow + (size_t)i * Hh * DI, nullptr, yt,
            Mm, Hh, DI, DI, DI, Hh);
        // x = LN(x + yt)
        ln_kernel<<<Mm, 128>>>(x, yt, lng + (size_t)i * Hh, lnb + (size_t)i * Hh);
    }

    // logits = x @ head_w.T + head_b    (2048 x 32000 x 512)
    gemm_nt<128,64,16,8,4,1><<<dim3(Mm/128, Vv/64), 256>>>(
        x, hw, hb, out, Mm, Vv, Hh, Hh, Hh, Vv);
}

// round 2
// speedup vs baseline: 1.3037x; 1.3037x over previous
#include <cuda_runtime.h>
#include <cstdint>
#include <math.h>

#define DEV_INLINE __device__ __forceinline__

// ---------------- problem constants ----------------
constexpr int Bb  = 8;
constexpr int Ll  = 256;
constexpr int Hh  = 512;
constexpr int Vv  = 32000;
constexpr int DI  = 1024;
constexpr int DS  = 16;
constexpr int DTR = 32;
constexpr int Mm  = Bb * Ll;          // 2048 rows
constexpr int TAa = 200, TTt = 100, ADa = 1024, TDd = 1024;

// ---------------- scratch ----------------
__device__ float g_x   [Mm * Hh];
__device__ float g_xz  [Mm * 2 * DI];
__device__ float g_xc  [Mm * DI];
__device__ float g_dbl [Mm * 64];
__device__ float g_dt  [Mm * DI];
__device__ float g_y   [Mm * DI];
__device__ float g_yt  [Mm * Hh];
__device__ float g_sa  [Bb * ADa];
__device__ float g_st  [Bb * TDd];
__device__ float g_pooled[Bb * Hh];
__device__ float g_cond  [Bb * Hh];

// ---------------- helpers ----------------
DEV_INLINE float warp_sum(float v) {
    #pragma unroll
    for (int o = 16; o; o >>= 1) v += __shfl_xor_sync(0xffffffffu, v, o);
    return v;
}
DEV_INLINE float softplus_f(float x) { return x > 20.f ? x : log1pf(__expf(x)); }
DEV_INLINE float silu_f(float x)     { return x / (1.f + __expf(-x)); }

DEV_INLINE unsigned long long pack2(float lo, float hi) {
    unsigned long long r;
    asm("mov.b64 %0,{%1,%2};" : "=l"(r) : "f"(lo), "f"(hi));
    return r;
}
DEV_INLINE void ffma2(unsigned long long& d, unsigned long long a, unsigned long long b) {
    asm("fma.rn.f32x2 %0,%1,%2,%0;" : "+l"(d) : "l"(a), "l"(b));
}
DEV_INLINE float2 unpack2(unsigned long long v) {
    float2 f;
    asm("mov.b64 {%0,%1},%2;" : "=f"(f.x), "=f"(f.y) : "l"(v));
    return f;
}
DEV_INLINE uint32_t f2tf(float f) {
    uint32_t r;
    asm("cvt.rna.tf32.f32 %0,%1;" : "=r"(r) : "f"(f));
    return r;
}

// =====================================================================
// f32x2-packed NT SGEMM (FFMA2): C[m,n] = sum_k A[m,k]*B[n,k]
// double-buffered smem, register-staged gmem loads. TN must be even.
// =====================================================================
template<int BM, int BN, int BK, int TM, int TN>
__global__ void gemm_f32x2(const float* __restrict__ A, const float* __restrict__ Bp,
                           float* __restrict__ C,
                           int M, int N, int K, int lda, int ldb, int ldc)
{
    constexpr int TX = BN / TN;
    constexpr int TY = BM / TM;
    constexpr int NT = TX * TY;
    constexpr int KC4 = BK / 4;
    constexpr int AL = BM * KC4 / NT;    // float4 A loads per thread
    constexpr int BL = BN * KC4 / NT;
    constexpr int NP = TN / 2;           // f32x2 pairs per row

    __shared__ float As[2][BK][BM + 4];
    __shared__ float Bs[2][BK][BN + 4];

    const int tid = threadIdx.x;
    const int tx = tid % TX, ty = tid / TX;
    const int bm = blockIdx.x * BM, bn = blockIdx.y * BN;

    unsigned long long acc[TM][NP];
    #pragma unroll
    for (int i = 0; i < TM; i++)
        #pragma unroll
        for (int j = 0; j < NP; j++) acc[i][j] = 0ull;

    float4 ra[AL], rb[BL];

    auto ldA = [&](int k0) {
        #pragma unroll
        for (int t = 0; t < AL; t++) {
            int f = tid + t * NT;
            ra[t] = *reinterpret_cast<const float4*>(A + (size_t)(bm + f / KC4) * lda + k0 + (f % KC4) * 4);
        }
    };
    auto ldB = [&](int k0) {
        #pragma unroll
        for (int t = 0; t < BL; t++) {
            int f = tid + t * NT;
            rb[t] = *reinterpret_cast<const float4*>(Bp + (size_t)(bn + f / KC4) * ldb + k0 + (f % KC4) * 4);
        }
    };
    auto stA = [&](int buf) {
        #pragma unroll
        for (int t = 0; t < AL; t++) {
            int f = tid + t * NT, row = f / KC4, c = f % KC4;
            As[buf][c*4+0][row] = ra[t].x; As[buf][c*4+1][row] = ra[t].y;
            As[buf][c*4+2][row] = ra[t].z; As[buf][c*4+3][row] = ra[t].w;
        }
    };
    auto stB = [&](int buf) {
        #pragma unroll
        for (int t = 0; t < BL; t++) {
            int f = tid + t * NT, row = f / KC4, c = f % KC4;
            Bs[buf][c*4+0][row] = rb[t].x; Bs[buf][c*4+1][row] = rb[t].y;
            Bs[buf][c*4+2][row] = rb[t].z; Bs[buf][c*4+3][row] = rb[t].w;
        }
    };

    ldA(0); ldB(0);
    stA(0); stB(0);
    __syncthreads();
    int buf = 0;

    for (int k0 = 0; k0 < K; k0 += BK) {
        bool more = (k0 + BK) < K;
        if (more) { ldA(k0 + BK); ldB(k0 + BK); }
        #pragma unroll
        for (int k = 0; k < BK; k++) {
            unsigned long long a2[TM], b2[NP];
            #pragma unroll
            for (int i = 0; i < TM; i++) {
                float av = As[buf][k][ty * TM + i];
                a2[i] = pack2(av, av);
            }
            #pragma unroll
            for (int j = 0; j < NP; j++) {
                float2 bv = *reinterpret_cast<const float2*>(&Bs[buf][k][tx * TN + j * 2]);
                b2[j] = pack2(bv.x, bv.y);
            }
            #pragma unroll
            for (int i = 0; i < TM; i++)
                #pragma unroll
                for (int j = 0; j < NP; j++) ffma2(acc[i][j], a2[i], b2[j]);
        }
        if (more) {
            stA(buf ^ 1); stB(buf ^ 1);
            __syncthreads();
            buf ^= 1;
        }
    }

    #pragma unroll
    for (int i = 0; i < TM; i++) {
        int m = bm + ty * TM + i;
        #pragma unroll
        for (int q = 0; q < NP / 2; q++) {
            float2 p0 = unpack2(acc[i][q * 2 + 0]);
            float2 p1 = unpack2(acc[i][q * 2 + 1]);
            float4 o = make_float4(p0.x, p0.y, p1.x, p1.y);
            *reinterpret_cast<float4*>(C + (size_t)m * ldc + bn + tx * TN + q * 4) = o;
        }
    }
}

// =====================================================================
// TF32 tensor-core GEMM (head): C = A @ B^T + bias
// block 128x128, BK=16, 256 threads (8 warps, 4x2), warp tile 32x64
// =====================================================================
__global__ void gemm_tf32(const float* __restrict__ A, const float* __restrict__ Bp,
                          const float* __restrict__ bias, float* __restrict__ C,
                          int M, int N, int K, int lda, int ldb, int ldc)
{
    constexpr int BM = 128, BN = 128, BK = 16, NT = 256;
    constexpr int KC4 = BK / 4;          // 4
    constexpr int AL = BM * KC4 / NT;    // 2
    __shared__ uint32_t As[2][BK][BM + 4];
    __shared__ uint32_t Bs[2][BK][BN + 4];

    const int tid = threadIdx.x;
    const int wid = tid >> 5, lane = tid & 31;
    const int qr = lane >> 2, qc = lane & 3;
    const int wm = wid & 3, wn = wid >> 2;   // 4 warps along M, 2 along N
    const int bm = blockIdx.x * BM, bn = blockIdx.y * BN;

    float acc[2][8][4];
    #pragma unroll
    for (int i = 0; i < 2; i++)
        #pragma unroll
        for (int j = 0; j < 8; j++)
            #pragma unroll
            for (int c = 0; c < 4; c++) acc[i][j][c] = 0.f;

    float4 ra[AL], rb[AL];
    auto ldA = [&](int k0) {
        #pragma unroll
        for (int t = 0; t < AL; t++) {
            int f = tid + t * NT;
            ra[t] = *reinterpret_cast<const float4*>(A + (size_t)(bm + f / KC4) * lda + k0 + (f % KC4) * 4);
            rb[t] = *reinterpret_cast<const float4*>(Bp + (size_t)(bn + f / KC4) * ldb + k0 + (f % KC4) * 4);
        }
    };
    auto stA = [&](int buf) {
        #pragma unroll
        for (int t = 0; t < AL; t++) {
            int f = tid + t * NT, row = f / KC4, c = f % KC4;
            As[buf][c*4+0][row] = f2tf(ra[t].x); As[buf][c*4+1][row] = f2tf(ra[t].y);
            As[buf][c*4+2][row] = f2tf(ra[t].z); As[buf][c*4+3][row] = f2tf(ra[t].w);
            Bs[buf][c*4+0][row] = f2tf(rb[t].x); Bs[buf][c*4+1][row] = f2tf(rb[t].y);
            Bs[buf][c*4+2][row] = f2tf(rb[t].z); Bs[buf][c*4+3][row] = f2tf(rb[t].w);
        }
    };

    ldA(0); stA(0);
    __syncthreads();
    int buf = 0;

    for (int k0 = 0; k0 < K; k0 += BK) {
        bool more = (k0 + BK) < K;
        if (more) ldA(k0 + BK);
        #pragma unroll
        for (int ks = 0; ks < 2; ks++) {
            int c0 = ks * 8;
            uint32_t af[2][4], bf[8][2];
            #pragma unroll
            for (int i = 0; i < 2; i++) {
                int mb = wm * 32 + i * 16 + qr;
                af[i][0] = As[buf][c0 + qc    ][mb];
                af[i][1] = As[buf][c0 + qc    ][mb + 8];
                af[i][2] = As[buf][c0 + qc + 4][mb];
                af[i][3] = As[buf][c0 + qc + 4][mb + 8];
            }
            #pragma unroll
            for (int j = 0; j < 8; j++) {
                int nb = wn * 64 + j * 8 + qr;
                bf[j][0] = Bs[buf][c0 + qc    ][nb];
                bf[j][1] = Bs[buf][c0 + qc + 4][nb];
            }
            #pragma unroll
            for (int i = 0; i < 2; i++)
                #pragma unroll
                for (int j = 0; j < 8; j++) {
                    asm volatile(
                        "mma.sync.aligned.m16n8k8.row.col.f32.tf32.tf32.f32 "
                        "{%0,%1,%2,%3}, {%4,%5,%6,%7}, {%8,%9}, {%0,%1,%2,%3};"
                        : "+f"(acc[i][j][0]), "+f"(acc[i][j][1]),
                          "+f"(acc[i][j][2]), "+f"(acc[i][j][3])
                        : "r"(af[i][0]), "r"(af[i][1]), "r"(af[i][2]), "r"(af[i][3]),
                          "r"(bf[j][0]), "r"(bf[j][1]));
                }
        }
        if (more) {
            stA(buf ^ 1);
            __syncthreads();
            buf ^= 1;
        }
    }

    #pragma unroll
    for (int i = 0; i < 2; i++) {
        #pragma unroll
        for (int j = 0; j < 8; j++) {
            int row = bm + wm * 32 + i * 16 + qr;
            int col = bn + wn * 64 + j * 8 + qc * 2;
            float b0 = bias ? bias[col] : 0.f;
            float b1 = bias ? bias[col + 1] : 0.f;
            *reinterpret_cast<float2*>(C + (size_t)row * ldc + col) =
                make_float2(acc[i][j][0] + b0, acc[i][j][1] + b1);
            *reinterpret_cast<float2*>(C + (size_t)(row + 8) * ldc + col) =
                make_float2(acc[i][j][2] + b0, acc[i][j][3] + b1);
        }
    }
}

// =====================================================================
// small NT SGEMM (kept for the skinny dbl / dt GEMMs)
// EPI: 0 = none, 2 = softplus(+bias)
// =====================================================================
template<int BM, int BN, int BK, int TM, int TN, int EPI>
__global__ void gemm_nt(const float* __restrict__ A, const float* __restrict__ Bp,
                        const float* __restrict__ bias, float* __restrict__ C,
                        int M, int N, int K, int lda, int ldb, int ldc)
{
    constexpr int TX = BN / TN;
    constexpr int TY = BM / TM;
    constexpr int NT = TX * TY;
    constexpr int KC4 = BK / 4;
    __shared__ float As[BK][BM + 4];
    __shared__ float Bs[BK][BN + 4];

    const int tid = threadIdx.x;
    const int tx = tid % TX, ty = tid / TX;
    const int bm = blockIdx.x * BM, bn = blockIdx.y * BN;

    float acc[TM][TN];
    #pragma unroll
    for (int i = 0; i < TM; i++)
        #pragma unroll
        for (int j = 0; j < TN; j++) acc[i][j] = 0.f;

    for (int k0 = 0; k0 < K; k0 += BK) {
        for (int f = tid; f < BM * KC4; f += NT) {
            int row = f / KC4, c = f % KC4;
            float4 v = *reinterpret_cast<const float4*>(A + (size_t)(bm + row) * lda + k0 + c * 4);
            As[c*4+0][row] = v.x; As[c*4+1][row] = v.y;
            As[c*4+2][row] = v.z; As[c*4+3][row] = v.w;
        }
        for (int f = tid; f < BN * KC4; f += NT) {
            int row = f / KC4, c = f % KC4;
            float4 v = *reinterpret_cast<const float4*>(Bp + (size_t)(bn + row) * ldb + k0 + c * 4);
            Bs[c*4+0][row] = v.x; Bs[c*4+1][row] = v.y;
            Bs[c*4+2][row] = v.z; Bs[c*4+3][row] = v.w;
        }
        __syncthreads();
        #pragma unroll
        for (int k = 0; k < BK; k++) {
            float a[TM], b[TN];
            #pragma unroll
            for (int i = 0; i < TM; i++) a[i] = As[k][ty * TM + i];
            #pragma unroll
            for (int j = 0; j < TN; j++) b[j] = Bs[k][tx * TN + j];
            #pragma unroll
            for (int i = 0; i < TM; i++)
                #pragma unroll
                for (int j = 0; j < TN; j++) acc[i][j] += a[i] * b[j];
        }
        __syncthreads();
    }

    #pragma unroll
    for (int i = 0; i < TM; i++) {
        int m = bm + ty * TM + i;
        float4 o;
        float* op = &o.x;
        #pragma unroll
        for (int j = 0; j < TN; j++) {
            float v = acc[i][j];
            if (EPI >= 1) v += bias[bn + tx * TN + j];
            if (EPI == 2) v = softplus_f(v);
            op[j] = v;
        }
        *reinterpret_cast<float4*>(C + (size_t)m * ldc + bn + tx * TN) = o;
    }
}

// ---------------- conditioning path ----------------
__global__ void sums_kernel(const float* __restrict__ af, const float* __restrict__ tf,
                            const unsigned char* __restrict__ am, const unsigned char* __restrict__ tm,
                            float* __restrict__ sa, float* __restrict__ st)
{
    int k = blockIdx.x * 256 + threadIdx.x;
    int b = blockIdx.y;
    float s = 0.f;
    for (int t = 0; t < TAa; t++)
        if (!am[b * TAa + t]) s += af[((size_t)(b * TAa + t)) * ADa + k];
    sa[b * ADa + k] = s;
    s = 0.f;
    for (int t = 0; t < TTt; t++)
        if (!tm[b * TTt + t]) s += tf[((size_t)(b * TTt + t)) * TDd + k];
    st[b * TDd + k] = s;
}

__global__ void pooled_kernel(const float* __restrict__ sa, const float* __restrict__ st,
                              const unsigned char* __restrict__ am, const unsigned char* __restrict__ tm,
                              const float* __restrict__ aw, const float* __restrict__ tw,
                              const float* __restrict__ ab, const float* __restrict__ tb,
                              const float* __restrict__ me, float* __restrict__ pooled)
{
    int b = blockIdx.x, tid = threadIdx.x, lane = tid & 31, w = tid >> 5;
    float na = 0.f, nt = 0.f;
    for (int t = 0; t < TAa; t++) na += am[b * TAa + t] ? 0.f : 1.f;
    for (int t = 0; t < TTt; t++) nt += tm[b * TTt + t] ? 0.f : 1.f;
    float denom = fmaxf(na + nt, 1.f);

    for (int h = w; h < Hh; h += 8) {
        float s = 0.f;
        for (int k = lane; k < ADa; k += 32)
            s += sa[b * ADa + k] * aw[(size_t)h * ADa + k]
               + st[b * TDd + k] * tw[(size_t)h * TDd + k];
        s = warp_sum(s);
        if (lane == 0) {
            float v = s + na * (ab[h] + me[h]) + nt * (tb[h] + me[Hh + h]);
            pooled[b * Hh + h] = v / denom;
        }
    }
}

__global__ void cond_kernel(const float* __restrict__ pooled, const float* __restrict__ cw,
                            const float* __restrict__ cb, float* __restrict__ cond)
{
    int b = blockIdx.x, tid = threadIdx.x, lane = tid & 31, w = tid >> 5;
    for (int h = w; h < Hh; h += 8) {
        float s = 0.f;
        for (int k = lane; k < Hh; k += 32)
            s += pooled[b * Hh + k] * cw[(size_t)h * Hh + k];
        s = warp_sum(s);
        if (lane == 0) cond[b * Hh + h] = s + cb[h];
    }
}

__global__ void embed_kernel(const int* __restrict__ ids, const float* __restrict__ te,
                             const float* __restrict__ pe, const float* __restrict__ cond,
                             float* __restrict__ x)
{
    int idx = blockIdx.x * 256 + threadIdx.x;
    int h = idx & (Hh - 1);
    int m = idx >> 9;
    int l = m & (Ll - 1);
    int b = m >> 8;
    x[idx] = te[(size_t)ids[m] * Hh + h] + pe[l * Hh + h] + cond[b * Hh + h];
}

// ---------------- mamba internals ----------------
__global__ void conv_silu_kernel(const float* __restrict__ xz, const float* __restrict__ cw,
                                 const float* __restrict__ cb, float* __restrict__ xc)
{
    int idx = blockIdx.x * 256 + threadIdx.x;
    int d = idx & (DI - 1);
    int m = idx >> 10;
    int t = m & (Ll - 1);
    float acc = cb[d];
    #pragma unroll
    for (int k = 0; k < 4; k++) {
        int tt = t + k - 3;
        if (tt >= 0) acc += xz[(size_t)(m + k - 3) * (2 * DI) + d] * cw[d * 4 + k];
    }
    xc[idx] = silu_f(acc);
}

__global__ void scan_kernel(const float* __restrict__ dt, const float* __restrict__ xc,
                            const float* __restrict__ dbl, const float* __restrict__ xz,
                            const float* __restrict__ Alog, const float* __restrict__ Dp,
                            float* __restrict__ y)
{
    int b = blockIdx.y;
    int sq = threadIdx.x & 3;
    int dloc = threadIdx.x >> 2;
    int d = blockIdx.x * 64 + dloc;

    float Av[4];
    #pragma unroll
    for (int j = 0; j < 4; j++) Av[j] = -__expf(Alog[d * DS + sq * 4 + j]);
    float h[4] = {0.f, 0.f, 0.f, 0.f};
    float Dd = Dp[d];

    int mbase = b * Ll;
    for (int t = 0; t < Ll; t++) {
        int m = mbase + t;
        float dtv = dt[(size_t)m * DI + d];
        float xcv = xc[(size_t)m * DI + d];
        float u = dtv * xcv;
        const float* dm = dbl + (size_t)m * 64;
        float yp = 0.f;
        #pragma unroll
        for (int j = 0; j < 4; j++) {
            float Bv = dm[DTR + sq * 4 + j];
            float Cv = dm[DTR + DS + sq * 4 + j];
            float e = __expf(dtv * Av[j]);
            h[j] = h[j] * e + u * Bv;
            yp += h[j] * Cv;
        }
        yp += __shfl_xor_sync(0xffffffffu, yp, 1);
        yp += __shfl_xor_sync(0xffffffffu, yp, 2);
        if (sq == 0) {
            float zv = xz[(size_t)m * (2 * DI) + DI + d];
            y[(size_t)m * DI + d] = (yp + Dd * xcv) * silu_f(zv);
        }
    }
}

__global__ void ln_kernel(float* __restrict__ x, const float* __restrict__ yt,
                          const float* __restrict__ g, const float* __restrict__ bb)
{
    int m = blockIdx.x;
    int tid = threadIdx.x;
    float v[4];
    float s = 0.f;
    #pragma unroll
    for (int j = 0; j < 4; j++) {
        int h = tid + j * 128;
        v[j] = x[(size_t)m * Hh + h] + yt[(size_t)m * Hh + h];
        s += v[j];
    }
    __shared__ float red[4];
    __shared__ float red2[4];
    s = warp_sum(s);
    if ((tid & 31) == 0) red[tid >> 5] = s;
    __syncthreads();
    float mu = (red[0] + red[1] + red[2] + red[3]) * (1.f / Hh);
    float s2 = 0.f;
    #pragma unroll
    for (int j = 0; j < 4; j++) { float dv = v[j] - mu; s2 += dv * dv; }
    s2 = warp_sum(s2);
    if ((tid & 31) == 0) red2[tid >> 5] = s2;
    __syncthreads();
    float var = (red2[0] + red2[1] + red2[2] + red2[3]) * (1.f / Hh);
    float sc = rsqrtf(var + 1e-5f);
    #pragma unroll
    for (int j = 0; j < 4; j++) {
        int h = tid + j * 128;
        x[(size_t)m * Hh + h] = (v[j] - mu) * sc * g[h] + bb[h];
    }
}

// ---------------- launch ----------------
extern "C" void kernel_launch(void* const* d_in, const int* in_sizes, int n_in,
                              void* d_out, int out_size)
{
    const int*   ids  = (const int*)  d_in[0];
    const float* af   = (const float*)d_in[1];
    const float* tf   = (const float*)d_in[2];
    const unsigned char* am = (const unsigned char*)d_in[3];
    const unsigned char* tm = (const unsigned char*)d_in[4];
    const float* te   = (const float*)d_in[5];
    const float* pe   = (const float*)d_in[6];
    const float* aw   = (const float*)d_in[7];
    const float* ab   = (const float*)d_in[8];
    const float* tw   = (const float*)d_in[9];
    const float* tb   = (const float*)d_in[10];
    const float* me   = (const float*)d_in[11];
    const float* cw   = (const float*)d_in[12];
    const float* cb   = (const float*)d_in[13];
    const float* ipw  = (const float*)d_in[14];
    const float* convw= (const float*)d_in[15];
    const float* convb= (const float*)d_in[16];
    const float* xpw  = (const float*)d_in[17];
    const float* dtw  = (const float*)d_in[18];
    const float* dtb  = (const float*)d_in[19];
    const float* Alog = (const float*)d_in[20];
    const float* Dp   = (const float*)d_in[21];
    const float* ow   = (const float*)d_in[22];
    const float* lng  = (const float*)d_in[23];
    const float* lnb  = (const float*)d_in[24];
    const float* hw   = (const float*)d_in[25];
    const float* hb   = (const float*)d_in[26];
    float* out = (float*)d_out;

    float *x, *xz, *xc, *dbl, *dt, *y, *yt, *sa, *st, *pooled, *cond;
    cudaGetSymbolAddress((void**)&x,   g_x);
    cudaGetSymbolAddress((void**)&xz,  g_xz);
    cudaGetSymbolAddress((void**)&xc,  g_xc);
    cudaGetSymbolAddress((void**)&dbl, g_dbl);
    cudaGetSymbolAddress((void**)&dt,  g_dt);
    cudaGetSymbolAddress((void**)&y,   g_y);
    cudaGetSymbolAddress((void**)&yt,  g_yt);
    cudaGetSymbolAddress((void**)&sa,  g_sa);
    cudaGetSymbolAddress((void**)&st,  g_st);
    cudaGetSymbolAddress((void**)&pooled, g_pooled);
    cudaGetSymbolAddress((void**)&cond,   g_cond);

    // conditioning
    sums_kernel  <<<dim3(ADa / 256, Bb), 256>>>(af, tf, am, tm, sa, st);
    pooled_kernel<<<Bb, 256>>>(sa, st, am, tm, aw, tw, ab, tb, me, pooled);
    cond_kernel  <<<Bb, 256>>>(pooled, cw, cb, cond);
    embed_kernel <<<(Mm * Hh) / 256, 256>>>(ids, te, pe, cond, x);

    for (int i = 0; i < 6; i++) {
        // xz = x @ in_proj.T     (2048 x 2048 x 512), fp32x2 FFMA2
        gemm_f32x2<128,128,16,8,8><<<dim3(Mm/128, (2*DI)/128), 256>>>(
            x, ipw + (size_t)i * 2 * DI * Hh, xz, Mm, 2*DI, Hh, Hh, Hh, 2*DI);
        // xc = silu(causal_conv(xz[:, :DI]))
        conv_silu_kernel<<<(Mm * DI) / 256, 256>>>(xz, convw + (size_t)i * DI * 4,
                                                   convb + (size_t)i * DI, xc);
        // dbl = xc @ x_proj.T    (2048 x 64 x 1024)
        gemm_nt<16,64,32,1,4,0><<<dim3(Mm/16, 1), 256>>>(
            xc, xpw + (size_t)i * 64 * DI, nullptr, dbl, Mm, 64, DI, DI, DI, 64);
        // dt = softplus(dbl[:, :32] @ dt_w.T + dt_b)   (2048 x 1024 x 32)
        gemm_nt<16,64,32,1,4,2><<<dim3(Mm/16, DI/64), 256>>>(
            dbl, dtw + (size_t)i * DI * DTR, dtb + (size_t)i * DI, dt,
            Mm, DI, DTR, 64, DTR, DI);
        // selective scan
        scan_kernel<<<dim3(DI/64, Bb), 256>>>(dt, xc, dbl, xz,
                                              Alog + (size_t)i * DI * DS,
                                              Dp + (size_t)i * DI, y);
        // yt = y @ out_w.T       (2048 x 512 x 1024), fp32x2 FFMA2
        gemm_f32x2<64,64,16,4,8><<<dim3(Mm/64, Hh/64), 128>>>(
            y, ow + (size_t)i * Hh * DI, yt, Mm, Hh, DI, DI, DI, Hh);
        // x = LN(x + yt)
        ln_kernel<<<Mm, 128>>>(x, yt, lng + (size_t)i * Hh, lnb + (size_t)i * Hh);
    }

    // logits = x @ head_w.T + head_b   (2048 x 32000 x 512), tf32 tensor core
    gemm_tf32<<<dim3(Mm/128, Vv/128), 256>>>(x, hw, hb, out, Mm, Vv, Hh, Hh, Hh, Vv);
}

// round 3
// speedup vs baseline: 1.5096x; 1.1579x over previous
#include <cuda_runtime.h>
#include <cstdint>
#include <math.h>

#define DEV_INLINE __device__ __forceinline__

// ---------------- problem constants ----------------
constexpr int Bb  = 8;
constexpr int Ll  = 256;
constexpr int Hh  = 512;
constexpr int Vv  = 32000;
constexpr int DI  = 1024;
constexpr int DS  = 16;
constexpr int DTR = 32;
constexpr int Mm  = Bb * Ll;          // 2048 rows
constexpr int TAa = 200, TTt = 100, ADa = 1024, TDd = 1024;

// ---------------- scratch ----------------
__device__ float g_x   [Mm * Hh];
__device__ float g_xz  [Mm * 2 * DI];
__device__ float g_xc  [Mm * DI];
__device__ float g_dbl [Mm * 64];
__device__ float g_dt  [Mm * DI];
__device__ float g_y   [Mm * DI];
__device__ float g_yt  [Mm * Hh];
__device__ float g_sa  [Bb * ADa];
__device__ float g_st  [Bb * TDd];
__device__ float g_pooled[Bb * Hh];
__device__ float g_cond  [Bb * Hh];

// ---------------- helpers ----------------
DEV_INLINE float warp_sum(float v) {
    #pragma unroll
    for (int o = 16; o; o >>= 1) v += __shfl_xor_sync(0xffffffffu, v, o);
    return v;
}
DEV_INLINE float softplus_f(float x) { return x > 20.f ? x : log1pf(__expf(x)); }
DEV_INLINE float silu_f(float x)     { return x / (1.f + __expf(-x)); }

DEV_INLINE uint32_t f2tf(float f) {
    uint32_t r;
    asm("cvt.rna.tf32.f32 %0,%1;" : "=r"(r) : "f"(f));
    return r;
}
DEV_INLINE uint32_t s2u(const void* p) {
    return (uint32_t)__cvta_generic_to_shared(p);
}
#define CP_ASYNC16(saddr, gptr) \
    asm volatile("cp.async.cg.shared.global [%0], [%1], 16;\n" :: "r"(saddr), "l"(gptr))
#define CP_COMMIT  asm volatile("cp.async.commit_group;\n" ::)
#define CP_WAIT(n) asm volatile("cp.async.wait_group %0;\n" :: "n"(n))

#define MMA_TF32(d, a0,a1,a2,a3, b0,b1)                                        \
    asm volatile(                                                              \
        "mma.sync.aligned.m16n8k8.row.col.f32.tf32.tf32.f32 "                  \
        "{%0,%1,%2,%3}, {%4,%5,%6,%7}, {%8,%9}, {%0,%1,%2,%3};"                \
        : "+f"(d[0]), "+f"(d[1]), "+f"(d[2]), "+f"(d[3])                       \
        : "r"(a0), "r"(a1), "r"(a2), "r"(a3), "r"(b0), "r"(b1))

// =====================================================================
// TF32 tensor-core NT GEMM:  C = A @ B^T (+bias)
// 256 threads = 8 warps (4 along M, 2 along N). BK=16, 2-stage cp.async.
// SPLIT_A=1: A = hi+lo tf32 split (removes A-side truncation error).
// EPI=1: add bias.
// =====================================================================
template<int BM, int BN, int SPLIT_A, int EPI>
__global__ void gemm_tc(const float* __restrict__ A, const float* __restrict__ Bp,
                        const float* __restrict__ bias, float* __restrict__ C,
                        int M, int N, int K, int lda, int ldb, int ldc)
{
    constexpr int BK = 16;
    constexpr int NT = 256;
    constexpr int IT = BM / 4 / 16;    // mma tiles per warp along M
    constexpr int JT = BN / 2 / 8;     // mma tiles per warp along N
    constexpr int LDS_ = BK + 4;       // 20 floats row stride (conflict-free)
    constexpr int AL = BM * 4 / NT;    // float4 copies per thread for A
    constexpr int BL = BN * 4 / NT;

    __shared__ float As[2][BM][LDS_];
    __shared__ float Bs[2][BN][LDS_];

    const int tid = threadIdx.x;
    const int wid = tid >> 5, lane = tid & 31;
    const int qr = lane >> 2, qc = lane & 3;
    const int wm = wid & 3, wn = wid >> 1 & 0 ? 0 : (wid >> 2);
    const int bm = blockIdx.x * BM, bn = blockIdx.y * BN;

    float acc[IT][JT][4];
    #pragma unroll
    for (int i = 0; i < IT; i++)
        #pragma unroll
        for (int j = 0; j < JT; j++)
            #pragma unroll
            for (int c = 0; c < 4; c++) acc[i][j][c] = 0.f;

    auto stage = [&](int buf, int k0) {
        #pragma unroll
        for (int t = 0; t < AL; t++) {
            int f = tid + t * NT, row = f >> 2, c = f & 3;
            CP_ASYNC16(s2u(&As[buf][row][c * 4]),
                       A + (size_t)(bm + row) * lda + k0 + c * 4);
        }
        #pragma unroll
        for (int t = 0; t < BL; t++) {
            int f = tid + t * NT, row = f >> 2, c = f & 3;
            CP_ASYNC16(s2u(&Bs[buf][row][c * 4]),
                       Bp + (size_t)(bn + row) * ldb + k0 + c * 4);
        }
        CP_COMMIT;
    };

    stage(0, 0);
    const int T = K / BK;
    for (int t = 0; t < T; t++) {
        if (t + 1 < T) { stage((t + 1) & 1, (t + 1) * BK); CP_WAIT(1); }
        else           { CP_WAIT(0); }
        __syncthreads();
        const int buf = t & 1;
        #pragma unroll
        for (int ks = 0; ks < 2; ks++) {
            const int c0 = ks * 8;
            uint32_t ah[IT][4], al[IT][4], bh[JT][2];
            #pragma unroll
            for (int i = 0; i < IT; i++) {
                int mb = wm * (IT * 16) + i * 16 + qr;
                float a0 = As[buf][mb    ][c0 + qc];
                float a1 = As[buf][mb + 8][c0 + qc];
                float a2 = As[buf][mb    ][c0 + qc + 4];
                float a3 = As[buf][mb + 8][c0 + qc + 4];
                ah[i][0] = f2tf(a0); ah[i][1] = f2tf(a1);
                ah[i][2] = f2tf(a2); ah[i][3] = f2tf(a3);
                if (SPLIT_A) {
                    al[i][0] = f2tf(a0 - __uint_as_float(ah[i][0]));
                    al[i][1] = f2tf(a1 - __uint_as_float(ah[i][1]));
                    al[i][2] = f2tf(a2 - __uint_as_float(ah[i][2]));
                    al[i][3] = f2tf(a3 - __uint_as_float(ah[i][3]));
                }
            }
            #pragma unroll
            for (int j = 0; j < JT; j++) {
                int nb = wn * (JT * 8) + j * 8 + qr;
                bh[j][0] = f2tf(Bs[buf][nb][c0 + qc]);
                bh[j][1] = f2tf(Bs[buf][nb][c0 + qc + 4]);
            }
            #pragma unroll
            for (int i = 0; i < IT; i++)
                #pragma unroll
                for (int j = 0; j < JT; j++) {
                    MMA_TF32(acc[i][j], ah[i][0], ah[i][1], ah[i][2], ah[i][3],
                             bh[j][0], bh[j][1]);
                    if (SPLIT_A)
                        MMA_TF32(acc[i][j], al[i][0], al[i][1], al[i][2], al[i][3],
                                 bh[j][0], bh[j][1]);
                }
        }
        __syncthreads();
    }

    #pragma unroll
    for (int i = 0; i < IT; i++) {
        #pragma unroll
        for (int j = 0; j < JT; j++) {
            int row = bm + wm * (IT * 16) + i * 16 + qr;
            int col = bn + wn * (JT * 8) + j * 8 + qc * 2;
            float b0 = 0.f, b1 = 0.f;
            if (EPI == 1) { b0 = bias[col]; b1 = bias[col + 1]; }
            *reinterpret_cast<float2*>(C + (size_t)row * ldc + col) =
                make_float2(acc[i][j][0] + b0, acc[i][j][1] + b1);
            *reinterpret_cast<float2*>(C + (size_t)(row + 8) * ldc + col) =
                make_float2(acc[i][j][2] + b0, acc[i][j][3] + b1);
        }
    }
}

// =====================================================================
// small NT SGEMM (skinny dbl / dt GEMMs). EPI: 0 none, 2 softplus(+bias)
// =====================================================================
template<int BM, int BN, int BK, int TM, int TN, int EPI>
__global__ void gemm_nt(const float* __restrict__ A, const float* __restrict__ Bp,
                        const float* __restrict__ bias, float* __restrict__ C,
                        int M, int N, int K, int lda, int ldb, int ldc)
{
    constexpr int TX = BN / TN;
    constexpr int TY = BM / TM;
    constexpr int NT = TX * TY;
    constexpr int KC4 = BK / 4;
    __shared__ float As[BK][BM + 4];
    __shared__ float Bs[BK][BN + 4];

    const int tid = threadIdx.x;
    const int tx = tid % TX, ty = tid / TX;
    const int bm = blockIdx.x * BM, bn = blockIdx.y * BN;

    float acc[TM][TN];
    #pragma unroll
    for (int i = 0; i < TM; i++)
        #pragma unroll
        for (int j = 0; j < TN; j++) acc[i][j] = 0.f;

    for (int k0 = 0; k0 < K; k0 += BK) {
        for (int f = tid; f < BM * KC4; f += NT) {
            int row = f / KC4, c = f % KC4;
            float4 v = *reinterpret_cast<const float4*>(A + (size_t)(bm + row) * lda + k0 + c * 4);
            As[c*4+0][row] = v.x; As[c*4+1][row] = v.y;
            As[c*4+2][row] = v.z; As[c*4+3][row] = v.w;
        }
        for (int f = tid; f < BN * KC4; f += NT) {
            int row = f / KC4, c = f % KC4;
            float4 v = *reinterpret_cast<const float4*>(Bp + (size_t)(bn + row) * ldb + k0 + c * 4);
            Bs[c*4+0][row] = v.x; Bs[c*4+1][row] = v.y;
            Bs[c*4+2][row] = v.z; Bs[c*4+3][row] = v.w;
        }
        __syncthreads();
        #pragma unroll
        for (int k = 0; k < BK; k++) {
            float a[TM], b[TN];
            #pragma unroll
            for (int i = 0; i < TM; i++) a[i] = As[k][ty * TM + i];
            #pragma unroll
            for (int j = 0; j < TN; j++) b[j] = Bs[k][tx * TN + j];
            #pragma unroll
            for (int i = 0; i < TM; i++)
                #pragma unroll
                for (int j = 0; j < TN; j++) acc[i][j] += a[i] * b[j];
        }
        __syncthreads();
    }

    #pragma unroll
    for (int i = 0; i < TM; i++) {
        int m = bm + ty * TM + i;
        float4 o;
        float* op = &o.x;
        #pragma unroll
        for (int j = 0; j < TN; j++) {
            float v = acc[i][j];
            if (EPI >= 1) v += bias[bn + tx * TN + j];
            if (EPI == 2) v = softplus_f(v);
            op[j] = v;
        }
        *reinterpret_cast<float4*>(C + (size_t)m * ldc + bn + tx * TN) = o;
    }
}

// ---------------- conditioning path ----------------
__global__ void sums_kernel(const float* __restrict__ af, const float* __restrict__ tf,
                            const unsigned char* __restrict__ am, const unsigned char* __restrict__ tm,
                            float* __restrict__ sa, float* __restrict__ st)
{
    int k = blockIdx.x * 256 + threadIdx.x;
    int b = blockIdx.y;
    float s = 0.f;
    for (int t = 0; t < TAa; t++)
        if (!am[b * TAa + t]) s += af[((size_t)(b * TAa + t)) * ADa + k];
    sa[b * ADa + k] = s;
    s = 0.f;
    for (int t = 0; t < TTt; t++)
        if (!tm[b * TTt + t]) s += tf[((size_t)(b * TTt + t)) * TDd + k];
    st[b * TDd + k] = s;
}

__global__ void pooled_kernel(const float* __restrict__ sa, const float* __restrict__ st,
                              const unsigned char* __restrict__ am, const unsigned char* __restrict__ tm,
                              const float* __restrict__ aw, const float* __restrict__ tw,
                              const float* __restrict__ ab, const float* __restrict__ tb,
                              const float* __restrict__ me, float* __restrict__ pooled)
{
    int b = blockIdx.x, tid = threadIdx.x, lane = tid & 31, w = tid >> 5;
    float na = 0.f, nt = 0.f;
    for (int t = 0; t < TAa; t++) na += am[b * TAa + t] ? 0.f : 1.f;
    for (int t = 0; t < TTt; t++) nt += tm[b * TTt + t] ? 0.f : 1.f;
    float denom = fmaxf(na + nt, 1.f);

    for (int h = w; h < Hh; h += 8) {
        float s = 0.f;
        for (int k = lane; k < ADa; k += 32)
            s += sa[b * ADa + k] * aw[(size_t)h * ADa + k]
               + st[b * TDd + k] * tw[(size_t)h * TDd + k];
        s = warp_sum(s);
        if (lane == 0) {
            float v = s + na * (ab[h] + me[h]) + nt * (tb[h] + me[Hh + h]);
            pooled[b * Hh + h] = v / denom;
        }
    }
}

__global__ void cond_kernel(const float* __restrict__ pooled, const float* __restrict__ cw,
                            const float* __restrict__ cb, float* __restrict__ cond)
{
    int b = blockIdx.x, tid = threadIdx.x, lane = tid & 31, w = tid >> 5;
    for (int h = w; h < Hh; h += 8) {
        float s = 0.f;
        for (int k = lane; k < Hh; k += 32)
            s += pooled[b * Hh + k] * cw[(size_t)h * Hh + k];
        s = warp_sum(s);
        if (lane == 0) cond[b * Hh + h] = s + cb[h];
    }
}

__global__ void embed_kernel(const int* __restrict__ ids, const float* __restrict__ te,
                             const float* __restrict__ pe, const float* __restrict__ cond,
                             float* __restrict__ x)
{
    int idx = blockIdx.x * 256 + threadIdx.x;
    int h = idx & (Hh - 1);
    int m = idx >> 9;
    int l = m & (Ll - 1);
    int b = m >> 8;
    x[idx] = te[(size_t)ids[m] * Hh + h] + pe[l * Hh + h] + cond[b * Hh + h];
}

// ---------------- mamba internals ----------------
__global__ void conv_silu_kernel(const float* __restrict__ xz, const float* __restrict__ cw,
                                 const float* __restrict__ cb, float* __restrict__ xc)
{
    int idx = blockIdx.x * 256 + threadIdx.x;
    int d = idx & (DI - 1);
    int m = idx >> 10;
    int t = m & (Ll - 1);
    float acc = cb[d];
    #pragma unroll
    for (int k = 0; k < 4; k++) {
        int tt = t + k - 3;
        if (tt >= 0) acc += xz[(size_t)(m + k - 3) * (2 * DI) + d] * cw[d * 4 + k];
    }
    xc[idx] = silu_f(acc);
}

__global__ void scan_kernel(const float* __restrict__ dt, const float* __restrict__ xc,
                            const float* __restrict__ dbl, const float* __restrict__ xz,
                            const float* __restrict__ Alog, const float* __restrict__ Dp,
                            float* __restrict__ y)
{
    int b = blockIdx.y;
    int sq = threadIdx.x & 3;
    int dloc = threadIdx.x >> 2;
    int d = blockIdx.x * 64 + dloc;

    float Av[4];
    #pragma unroll
    for (int j = 0; j < 4; j++) Av[j] = -__expf(Alog[d * DS + sq * 4 + j]);
    float h[4] = {0.f, 0.f, 0.f, 0.f};
    float Dd = Dp[d];

    int mbase = b * Ll;
    for (int t = 0; t < Ll; t++) {
        int m = mbase + t;
        float dtv = dt[(size_t)m * DI + d];
        float xcv = xc[(size_t)m * DI + d];
        float u = dtv * xcv;
        const float* dm = dbl + (size_t)m * 64;
        float yp = 0.f;
        #pragma unroll
        for (int j = 0; j < 4; j++) {
            float Bv = dm[DTR + sq * 4 + j];
            float Cv = dm[DTR + DS + sq * 4 + j];
            float e = __expf(dtv * Av[j]);
            h[j] = h[j] * e + u * Bv;
            yp += h[j] * Cv;
        }
        yp += __shfl_xor_sync(0xffffffffu, yp, 1);
        yp += __shfl_xor_sync(0xffffffffu, yp, 2);
        if (sq == 0) {
            float zv = xz[(size_t)m * (2 * DI) + DI + d];
            y[(size_t)m * DI + d] = (yp + Dd * xcv) * silu_f(zv);
        }
    }
}

__global__ void ln_kernel(float* __restrict__ x, const float* __restrict__ yt,
                          const float* __restrict__ g, const float* __restrict__ bb)
{
    int m = blockIdx.x;
    int tid = threadIdx.x;
    float v[4];
    float s = 0.f;
    #pragma unroll
    for (int j = 0; j < 4; j++) {
        int h = tid + j * 128;
        v[j] = x[(size_t)m * Hh + h] + yt[(size_t)m * Hh + h];
        s += v[j];
    }
    __shared__ float red[4];
    __shared__ float red2[4];
    s = warp_sum(s);
    if ((tid & 31) == 0) red[tid >> 5] = s;
    __syncthreads();
    float mu = (red[0] + red[1] + red[2] + red[3]) * (1.f / Hh);
    float s2 = 0.f;
    #pragma unroll
    for (int j = 0; j < 4; j++) { float dv = v[j] - mu; s2 += dv * dv; }
    s2 = warp_sum(s2);
    if ((tid & 31) == 0) red2[tid >> 5] = s2;
    __syncthreads();
    float var = (red2[0] + red2[1] + red2[2] + red2[3]) * (1.f / Hh);
    float sc = rsqrtf(var + 1e-5f);
    #pragma unroll
    for (int j = 0; j < 4; j++) {
        int h = tid + j * 128;
        x[(size_t)m * Hh + h] = (v[j] - mu) * sc * g[h] + bb[h];
    }
}

// ---------------- launch ----------------
extern "C" void kernel_launch(void* const* d_in, const int* in_sizes, int n_in,
                              void* d_out, int out_size)
{
    const int*   ids  = (const int*)  d_in[0];
    const float* af   = (const float*)d_in[1];
    const float* tf   = (const float*)d_in[2];
    const unsigned char* am = (const unsigned char*)d_in[3];
    const unsigned char* tm = (const unsigned char*)d_in[4];
    const float* te   = (const float*)d_in[5];
    const float* pe   = (const float*)d_in[6];
    const float* aw   = (const float*)d_in[7];
    const float* ab   = (const float*)d_in[8];
    const float* tw   = (const float*)d_in[9];
    const float* tb   = (const float*)d_in[10];
    const float* me   = (const float*)d_in[11];
    const float* cw   = (const float*)d_in[12];
    const float* cb   = (const float*)d_in[13];
    const float* ipw  = (const float*)d_in[14];
    const float* convw= (const float*)d_in[15];
    const float* convb= (const float*)d_in[16];
    const float* xpw  = (const float*)d_in[17];
    const float* dtw  = (const float*)d_in[18];
    const float* dtb  = (const float*)d_in[19];
    const float* Alog = (const float*)d_in[20];
    const float* Dp   = (const float*)d_in[21];
    const float* ow   = (const float*)d_in[22];
    const float* lng  = (const float*)d_in[23];
    const float* lnb  = (const float*)d_in[24];
    const float* hw   = (const float*)d_in[25];
    const float* hb   = (const float*)d_in[26];
    float* out = (float*)d_out;

    float *x, *xz, *xc, *dbl, *dt, *y, *yt, *sa, *st, *pooled, *cond;
    cudaGetSymbolAddress((void**)&x,   g_x);
    cudaGetSymbolAddress((void**)&xz,  g_xz);
    cudaGetSymbolAddress((void**)&xc,  g_xc);
    cudaGetSymbolAddress((void**)&dbl, g_dbl);
    cudaGetSymbolAddress((void**)&dt,  g_dt);
    cudaGetSymbolAddress((void**)&y,   g_y);
    cudaGetSymbolAddress((void**)&yt,  g_yt);
    cudaGetSymbolAddress((void**)&sa,  g_sa);
    cudaGetSymbolAddress((void**)&st,  g_st);
    cudaGetSymbolAddress((void**)&pooled, g_pooled);
    cudaGetSymbolAddress((void**)&cond,   g_cond);

    // conditioning
    sums_kernel  <<<dim3(ADa / 256, Bb), 256>>>(af, tf, am, tm, sa, st);
    pooled_kernel<<<Bb, 256>>>(sa, st, am, tm, aw, tw, ab, tb, me, pooled);
    cond_kernel  <<<Bb, 256>>>(pooled, cw, cb, cond);
    embed_kernel <<<(Mm * Hh) / 256, 256>>>(ids, te, pe, cond, x);

    for (int i = 0; i < 6; i++) {
        // xz = x @ in_proj.T   (2048 x 2048 x 512), tf32 split-A
        gemm_tc<128,128,1,0><<<dim3(Mm/128, (2*DI)/128), 256>>>(
            x, ipw + (size_t)i * 2 * DI * Hh, nullptr, xz, Mm, 2*DI, Hh, Hh, Hh, 2*DI);
        // xc = silu(causal_conv(xz[:, :DI]))
        conv_silu_kernel<<<(Mm * DI) / 256, 256>>>(xz, convw + (size_t)i * DI * 4,
                                                   convb + (size_t)i * DI, xc);
        // dbl = xc @ x_proj.T  (2048 x 64 x 1024)
        gemm_nt<16,64,32,1,4,0><<<dim3(Mm/16, 1), 256>>>(
            xc, xpw + (size_t)i * 64 * DI, nullptr, dbl, Mm, 64, DI, DI, DI, 64);
        // dt = softplus(dbl[:, :32] @ dt_w.T + dt_b)  (2048 x 1024 x 32)
        gemm_nt<16,64,32,1,4,2><<<dim3(Mm/16, DI/64), 256>>>(
            dbl, dtw + (size_t)i * DI * DTR, dtb + (size_t)i * DI, dt,
            Mm, DI, DTR, 64, DTR, DI);
        // selective scan
        scan_kernel<<<dim3(DI/64, Bb), 256>>>(dt, xc, dbl, xz,
                                              Alog + (size_t)i * DI * DS,
                                              Dp + (size_t)i * DI, y);
        // yt = y @ out_w.T     (2048 x 512 x 1024), tf32 split-A
        gemm_tc<128,64,1,0><<<dim3(Mm/128, Hh/64), 256>>>(
            y, ow + (size_t)i * Hh * DI, nullptr, yt, Mm, Hh, DI, DI, DI, Hh);
        // x = LN(x + yt)
        ln_kernel<<<Mm, 128>>>(x, yt, lng + (size_t)i * Hh, lnb + (size_t)i * Hh);
    }

    // logits = x @ head_w.T + head_b  (2048 x 32000 x 512), tf32 single-pass
    gemm_tc<128,128,0,1><<<dim3(Mm/128, Vv/128), 256>>>(
        x, hw, hb, out, Mm, Vv, Hh, Hh, Hh, Vv);
}